// round 7
// baseline (speedup 1.0000x reference)
#include <cuda_runtime.h>
#include <math.h>

#define BLK      256
#define NW       8          // warps per block
#define CHUNK    128        // pred points per item
#define MAX_P    2048
#define MAX_B    64
#define NBLOCKS  608
#define MAX_ITEMS 4096

// cos(7.5 degrees): ang > 15deg  <=>  |dot| < cos(7.5deg)
#define COS_HALF_HARD 0.9914448613738104f

__device__ unsigned g_ctr  = 0;
__device__ unsigned g_done = 0;
__device__ float    g_part[MAX_ITEMS];
__device__ int      g_flags[MAX_B];      // 0=skip, 1=direct, 2=closest
// pair-transposed rotated gt cloud: [b][2i]={gx0,gx1,gy0,gy1} [b][2i+1]={gz0,gz1,h0,h1}
__device__ float4   g_gt[MAX_B * MAX_P];
// rotated pred cloud: [b][p] = {px,py,pz,0}
__device__ float4   g_pr[MAX_B * MAX_P];

__device__ __forceinline__ float sl1(float v) {
    float a = fabsf(v);
    return (a < 1.f) ? 0.5f * v * v : a - 0.5f;
}

__device__ __forceinline__ void quat2rot(float w, float x, float y, float z, float* R) {
    R[0] = 1.f - 2.f * (y * y + z * z);
    R[1] = 2.f * (x * y - z * w);
    R[2] = 2.f * (x * z + y * w);
    R[3] = 2.f * (x * y + z * w);
    R[4] = 1.f - 2.f * (x * x + z * z);
    R[5] = 2.f * (y * z - x * w);
    R[6] = 2.f * (x * z - y * w);
    R[7] = 2.f * (y * z + x * w);
    R[8] = 1.f - 2.f * (x * x + y * y);
}

// Blackwell packed f32x2 FMA (SASS FFMA2) — only reachable via PTX.
__device__ __forceinline__ unsigned long long ffma2(unsigned long long a,
                                                    unsigned long long b,
                                                    unsigned long long c) {
    unsigned long long d;
    asm("fma.rn.f32x2 %0, %1, %2, %3;" : "=l"(d) : "l"(a), "l"(b), "l"(c));
    return d;
}

__device__ __forceinline__ unsigned long long pack2(float lo, float hi) {
    unsigned long long d;
    asm("mov.b64 %0, {%1, %2};" : "=l"(d)
        : "r"(__float_as_uint(lo)), "r"(__float_as_uint(hi)));
    return d;
}

__device__ __forceinline__ void unpack2(unsigned long long v,
                                        unsigned& lo, unsigned& hi) {
    asm("mov.b64 {%0, %1}, %2;" : "=r"(lo), "=r"(hi) : "l"(v));
}

// ---------- pre-pass: rotate both clouds for every sample into scratch ----------
__global__ void __launch_bounds__(BLK)
pm_rotate(const float* __restrict__ pred,
          const float* __restrict__ tgt,
          const float* __restrict__ w,
          const float* __restrict__ sym,
          const float* __restrict__ points,
          int B, int C, int P) {
    const int b   = blockIdx.x;
    const int tid = threadIdx.x;
    if (b >= B) return;

    // every thread computes sample setup redundantly (cheap, uniform)
    int cls = 0, valid = 0;
    for (int c = 0; c < C; ++c) {
        if (__ldg(&w[(size_t)(b * C + c) * 4]) > 0.f) { cls = c; valid = 1; break; }
    }
    float Rp[9], Rg[9];
    const float* qp = pred + (size_t)(b * C + cls) * 4;
    const float* qg = tgt  + (size_t)(b * C + cls) * 4;
    float pw = __ldg(qp + 0), px_ = __ldg(qp + 1), py_ = __ldg(qp + 2), pz_ = __ldg(qp + 3);
    float gw = __ldg(qg + 0), gx_ = __ldg(qg + 1), gy_ = __ldg(qg + 2), gz_ = __ldg(qg + 3);
    quat2rot(pw, px_, py_, pz_, Rp);
    quat2rot(gw, gx_, gy_, gz_, Rg);
    float dot = fabsf(pw * gw + px_ * gx_ + py_ * gy_ + pz_ * gz_);
    int use_closest = (__ldg(&sym[cls]) > 0.f) && (dot < COS_HALF_HARD);
    if (tid == 0) g_flags[b] = valid ? (use_closest ? 2 : 1) : 0;
    if (!valid) return;

    const float* pt   = points + (size_t)cls * P * 3;
    const int    HALF = (P + 1) >> 1;

    for (int i = tid; i < HALF; i += BLK) {
        int q0 = 2 * i, q1 = 2 * i + 1;
        float x0 = __ldg(&pt[3 * q0 + 0]);
        float y0 = __ldg(&pt[3 * q0 + 1]);
        float z0 = __ldg(&pt[3 * q0 + 2]);
        float x1 = 0.f, y1 = 0.f, z1 = 0.f;
        int in1 = (q1 < P);
        if (in1) {
            x1 = __ldg(&pt[3 * q1 + 0]);
            y1 = __ldg(&pt[3 * q1 + 1]);
            z1 = __ldg(&pt[3 * q1 + 2]);
        }
        // gt rotations
        float g0x = Rg[0] * x0 + Rg[1] * y0 + Rg[2] * z0;
        float g0y = Rg[3] * x0 + Rg[4] * y0 + Rg[5] * z0;
        float g0z = Rg[6] * x0 + Rg[7] * y0 + Rg[8] * z0;
        float h0  = 0.5f * (g0x * g0x + g0y * g0y + g0z * g0z);
        float g1x = 0.f, g1y = 0.f, g1z = 0.f, h1 = 3.0e38f;
        if (in1) {
            g1x = Rg[0] * x1 + Rg[1] * y1 + Rg[2] * z1;
            g1y = Rg[3] * x1 + Rg[4] * y1 + Rg[5] * z1;
            g1z = Rg[6] * x1 + Rg[7] * y1 + Rg[8] * z1;
            h1  = 0.5f * (g1x * g1x + g1y * g1y + g1z * g1z);
        }
        g_gt[b * MAX_P + 2 * i]     = make_float4(g0x, g1x, g0y, g1y);
        g_gt[b * MAX_P + 2 * i + 1] = make_float4(g0z, g1z, h0, h1);
        // pred rotations
        float p0x = Rp[0] * x0 + Rp[1] * y0 + Rp[2] * z0;
        float p0y = Rp[3] * x0 + Rp[4] * y0 + Rp[5] * z0;
        float p0z = Rp[6] * x0 + Rp[7] * y0 + Rp[8] * z0;
        g_pr[b * MAX_P + q0] = make_float4(p0x, p0y, p0z, 0.f);
        if (in1) {
            float p1x = Rp[0] * x1 + Rp[1] * y1 + Rp[2] * z1;
            float p1y = Rp[3] * x1 + Rp[4] * y1 + Rp[5] * z1;
            float p1z = Rp[6] * x1 + Rp[7] * y1 + Rp[8] * z1;
            g_pr[b * MAX_P + q1] = make_float4(p1x, p1y, p1z, 0.f);
        }
    }
}

// one scan step over a q-pair for 4 independent pred chains
#define SCAN_STEP(VA, VB, I)                                               \
    do {                                                                   \
        _Pragma("unroll")                                                  \
        for (int j = 0; j < 4; ++j) {                                      \
            unsigned long long t2 = ffma2(npzz[j], (VB).x, (VB).y);        \
            t2 = ffma2(npyy[j], (VA).y, t2);                               \
            t2 = ffma2(npxx[j], (VA).x, t2);                               \
            unsigned tlo, thi;                                             \
            unpack2(t2, tlo, thi);                                         \
            float m2 = fminf(__uint_as_float(tlo), __uint_as_float(thi));  \
            unsigned km = (__float_as_uint(m2) & 0xFFFFFC00u) | (unsigned)(I); \
            best[j] = fminf(best[j], __uint_as_float(km));                 \
        }                                                                  \
    } while (0)

// ---------- hot kernel: persistent work queue over (sample, chunk) items ----------
__global__ void __launch_bounds__(BLK, 4)
pm_scan(int P, int CHUNKS, int NITEMS, float inv, float* __restrict__ out) {
    __shared__ float4   sg2[MAX_P];
    __shared__ float    sbest[NW * CHUNK];
    __shared__ float    sred[NW];
    __shared__ unsigned s_item;

    const int tid  = threadIdx.x;
    const int wid  = tid >> 5;
    const int lane = tid & 31;

    int fill_b = -1;
    const int HALF = (P + 1) >> 1;
    const int PPW  = (HALF + NW - 1) / NW;

    for (;;) {
        if (tid == 0) s_item = atomicAdd(&g_ctr, 1u);
        __syncthreads();
        unsigned it = s_item;
        if (it >= (unsigned)NITEMS) break;

        const int b     = (int)(it / (unsigned)CHUNKS);
        const int chunk = (int)(it % (unsigned)CHUNKS);
        const int flag  = g_flags[b];
        const int pbase = chunk * CHUNK;

        float lsum = 0.f;

        if (flag == 2) {
            // --- load this lane's 4 prerotated pred points (4 indep LDG.128) ---
            unsigned long long npxx[4], npyy[4], npzz[4];
#pragma unroll
            for (int j = 0; j < 4; ++j) {
                int p = pbase + lane + 32 * j;
                float4 pp = (p < P) ? g_pr[b * MAX_P + p] : make_float4(0.f, 0.f, 0.f, 0.f);
                npxx[j] = pack2(-pp.x, -pp.x);
                npyy[j] = pack2(-pp.y, -pp.y);
                npzz[j] = pack2(-pp.z, -pp.z);
            }

            // --- fill: pure float4 copy, 8 independent loads per thread ---
            if (fill_b != b) {
                const float4* src = &g_gt[b * MAX_P];
#pragma unroll 8
                for (int i = tid; i < 2 * HALF; i += BLK)
                    sg2[i] = __ldg(&src[i]);
                fill_b = b;
            }
            __syncthreads();

            // --- warp scans its q-pair slice; 4 independent fmin chains ---
            float best[4];
#pragma unroll
            for (int j = 0; j < 4; ++j) best[j] = __uint_as_float(0x7F7FFFFFu);

            const ulonglong2* sgu = reinterpret_cast<const ulonglong2*>(sg2);

            if (P == 2048) {
                const int i0 = wid * 128;
                const ulonglong2* pg = sgu + 2 * i0;
#pragma unroll 4
                for (int ii = 0; ii < 128; ++ii) {
                    ulonglong2 va = pg[0];
                    ulonglong2 vb = pg[1];
                    pg += 2;
                    SCAN_STEP(va, vb, i0 + ii);
                }
            } else {
                const int i0 = wid * PPW;
                const int i1 = min(i0 + PPW, HALF);
#pragma unroll 2
                for (int i = i0; i < i1; ++i) {
                    ulonglong2 va = sgu[2 * i];
                    ulonglong2 vb = sgu[2 * i + 1];
                    SCAN_STEP(va, vb, i);
                }
            }
#pragma unroll
            for (int j = 0; j < 4; ++j)
                sbest[wid * CHUNK + lane + 32 * j] = best[j];
            __syncthreads();

            // --- thread t (<128) finalizes pred point pbase+t ---
            if (tid < CHUNK) {
                int p = pbase + tid;
                if (p < P) {
                    float m = sbest[tid];
#pragma unroll
                    for (int ww = 1; ww < NW; ++ww)
                        m = fminf(m, sbest[ww * CHUNK + tid]);
                    int k = (int)(__float_as_uint(m) & 0x3FFu);   // pair index

                    float4 pp = g_pr[b * MAX_P + p];
                    float4 A  = sg2[2 * k];
                    float4 Bv = sg2[2 * k + 1];
                    // recompute both t's bit-identically to the FFMA2 path
                    float t0 = fmaf(-pp.x, A.x, fmaf(-pp.y, A.z, fmaf(-pp.z, Bv.x, Bv.z)));
                    float t1 = fmaf(-pp.x, A.y, fmaf(-pp.y, A.w, fmaf(-pp.z, Bv.y, Bv.w)));
                    float gx, gy, gz;
                    if (t1 < t0) { gx = A.y; gy = A.w; gz = Bv.y; }
                    else         { gx = A.x; gy = A.z; gz = Bv.x; }
                    lsum = sl1(pp.x - gx) + sl1(pp.y - gy) + sl1(pp.z - gz);
                }
            }
        } else if (flag == 1) {
            // direct match: p_pred vs p_gt at same index; read scratch, no SMEM
            if (tid < CHUNK) {
                int p = pbase + tid;
                if (p < P) {
                    float4 pp = g_pr[b * MAX_P + p];
                    int k = p >> 1, h = p & 1;
                    float4 A  = g_gt[b * MAX_P + 2 * k];
                    float4 Bv = g_gt[b * MAX_P + 2 * k + 1];
                    float gx = h ? A.y  : A.x;
                    float gy = h ? A.w  : A.z;
                    float gz = h ? Bv.y : Bv.x;
                    lsum = sl1(pp.x - gx) + sl1(pp.y - gy) + sl1(pp.z - gz);
                }
            }
        }

        // deterministic per-item reduce (shuffle tree + fixed-order warp merge)
#pragma unroll
        for (int off = 16; off > 0; off >>= 1)
            lsum += __shfl_down_sync(0xFFFFFFFFu, lsum, off);
        if (lane == 0) sred[wid] = lsum;
        __syncthreads();
        if (tid == 0) {
            float s = 0.f;
#pragma unroll
            for (int ww = 0; ww < NW; ++ww) s += sred[ww];
            g_part[it] = s;
        }
    }

    // last-block final reduction (fixed order -> deterministic)
    __syncthreads();
    if (tid == 0) {
        __threadfence();
        unsigned d = atomicAdd(&g_done, 1u);
        s_item = (d == gridDim.x - 1) ? 1u : 0u;
    }
    __syncthreads();
    if (s_item) {
        __threadfence();
        float v = 0.f;
        for (int i = tid; i < NITEMS; i += BLK) v += g_part[i];
        sbest[tid] = v;
        __syncthreads();
#pragma unroll
        for (int st = BLK / 2; st > 0; st >>= 1) {
            if (tid < st) sbest[tid] += sbest[tid + st];
            __syncthreads();
        }
        if (tid == 0) {
            out[0] = sbest[0] * inv;
            g_ctr  = 0;
            g_done = 0;
        }
    }
}

extern "C" void kernel_launch(void* const* d_in, const int* in_sizes, int n_in,
                              void* d_out, int out_size) {
    const float* pred = (const float*)d_in[0];
    const float* tgt  = (const float*)d_in[1];
    const float* w    = (const float*)d_in[2];
    const float* pts  = (const float*)d_in[3];
    const float* sym  = (const float*)d_in[4];

    int C = in_sizes[4];
    int B = in_sizes[0] / (4 * C);
    int P = in_sizes[3] / (3 * C);
    int CHUNKS = (P + CHUNK - 1) / CHUNK;
    int NITEMS = B * CHUNKS;

    pm_rotate<<<B, BLK>>>(pred, tgt, w, sym, pts, B, C, P);
    pm_scan<<<NBLOCKS, BLK>>>(P, CHUNKS, NITEMS, 1.f / (float)(B * P), (float*)d_out);
}

// round 8
// speedup vs baseline: 1.1159x; 1.1159x over previous
#include <cuda_runtime.h>
#include <math.h>

#define BLK      256
#define NW       8          // warps per block
#define CHUNK    128        // pred points per item
#define MAX_P    2048
#define MAX_B    64
#define NBLOCKS  608
#define MAX_ITEMS 4096

// cos(7.5 degrees): ang > 15deg  <=>  |dot| < cos(7.5deg)
#define COS_HALF_HARD 0.9914448613738104f

__device__ unsigned g_ctr  = 0;
__device__ unsigned g_done = 0;
__device__ float    g_part[MAX_ITEMS];
__device__ int      g_ready[MAX_B];      // 0=pending, 1=skip, 2=direct, 3=closest
// pair-transposed rotated gt cloud: [b][2i]={gx0,gx1,gy0,gy1} [b][2i+1]={gz0,gz1,h0,h1}
__device__ float4   g_gt[MAX_B * MAX_P];
// rotated pred cloud: [b][p] = {px,py,pz,0}
__device__ float4   g_pr[MAX_B * MAX_P];

__device__ __forceinline__ float sl1(float v) {
    float a = fabsf(v);
    return (a < 1.f) ? 0.5f * v * v : a - 0.5f;
}

__device__ __forceinline__ void quat2rot(float w, float x, float y, float z, float* R) {
    R[0] = 1.f - 2.f * (y * y + z * z);
    R[1] = 2.f * (x * y - z * w);
    R[2] = 2.f * (x * z + y * w);
    R[3] = 2.f * (x * y + z * w);
    R[4] = 1.f - 2.f * (x * x + z * z);
    R[5] = 2.f * (y * z - x * w);
    R[6] = 2.f * (x * z - y * w);
    R[7] = 2.f * (y * z + x * w);
    R[8] = 1.f - 2.f * (x * x + y * y);
}

// Blackwell packed f32x2 FMA (SASS FFMA2) — only reachable via PTX.
__device__ __forceinline__ unsigned long long ffma2(unsigned long long a,
                                                    unsigned long long b,
                                                    unsigned long long c) {
    unsigned long long d;
    asm("fma.rn.f32x2 %0, %1, %2, %3;" : "=l"(d) : "l"(a), "l"(b), "l"(c));
    return d;
}

__device__ __forceinline__ unsigned long long pack2(float lo, float hi) {
    unsigned long long d;
    asm("mov.b64 %0, {%1, %2};" : "=l"(d)
        : "r"(__float_as_uint(lo)), "r"(__float_as_uint(hi)));
    return d;
}

__device__ __forceinline__ void unpack2(unsigned long long v,
                                        unsigned& lo, unsigned& hi) {
    asm("mov.b64 {%0, %1}, %2;" : "=r"(lo), "=r"(hi) : "l"(v));
}

// one scan step over a q-pair for 4 independent pred chains
#define SCAN_STEP(VA, VB, I)                                               \
    do {                                                                   \
        _Pragma("unroll")                                                  \
        for (int j = 0; j < 4; ++j) {                                      \
            unsigned long long t2 = ffma2(npzz[j], (VB).x, (VB).y);        \
            t2 = ffma2(npyy[j], (VA).y, t2);                               \
            t2 = ffma2(npxx[j], (VA).x, t2);                               \
            unsigned tlo, thi;                                             \
            unpack2(t2, tlo, thi);                                         \
            float m2 = fminf(__uint_as_float(tlo), __uint_as_float(thi));  \
            unsigned km = (__float_as_uint(m2) & 0xFFFFFC00u) | (unsigned)(I); \
            best[j] = fminf(best[j], __uint_as_float(km));                 \
        }                                                                  \
    } while (0)

__global__ void __launch_bounds__(BLK, 4)
pm_all(const float* __restrict__ pred,
       const float* __restrict__ tgt,
       const float* __restrict__ w,
       const float* __restrict__ sym,
       const float* __restrict__ points,
       int B, int C, int P, int CHUNKS, int NITEMS,
       float inv, float* __restrict__ out) {
    __shared__ float4   sg2[MAX_P];          // pair-transposed gt tile
    __shared__ float    sbest[NW * CHUNK];
    __shared__ float    sred[NW];
    __shared__ unsigned s_u[2];              // [0]=item, [1]=flag

    const int tid  = threadIdx.x;
    const int wid  = tid >> 5;
    const int lane = tid & 31;
    const int HALF = (P + 1) >> 1;
    const int PPW  = (HALF + NW - 1) / NW;

    // ---------- phase 1: blocks 0..B-1 rotate their sample, publish flag ----------
    if ((int)blockIdx.x < B) {
        const int b = blockIdx.x;
        int cls = 0, valid = 0;
        for (int c = 0; c < C; ++c) {
            if (__ldg(&w[(size_t)(b * C + c) * 4]) > 0.f) { cls = c; valid = 1; break; }
        }
        float Rp[9], Rg[9];
        const float* qp = pred + (size_t)(b * C + cls) * 4;
        const float* qg = tgt  + (size_t)(b * C + cls) * 4;
        float pw = __ldg(qp + 0), px_ = __ldg(qp + 1), py_ = __ldg(qp + 2), pz_ = __ldg(qp + 3);
        float gw = __ldg(qg + 0), gx_ = __ldg(qg + 1), gy_ = __ldg(qg + 2), gz_ = __ldg(qg + 3);
        quat2rot(pw, px_, py_, pz_, Rp);
        quat2rot(gw, gx_, gy_, gz_, Rg);
        float dot = fabsf(pw * gw + px_ * gx_ + py_ * gy_ + pz_ * gz_);
        int use_closest = (__ldg(&sym[cls]) > 0.f) && (dot < COS_HALF_HARD);

        if (valid) {
            const float* pt = points + (size_t)cls * P * 3;
            for (int i = tid; i < HALF; i += BLK) {
                int q0 = 2 * i, q1 = 2 * i + 1;
                float x0 = __ldg(&pt[3 * q0 + 0]);
                float y0 = __ldg(&pt[3 * q0 + 1]);
                float z0 = __ldg(&pt[3 * q0 + 2]);
                float x1 = 0.f, y1 = 0.f, z1 = 0.f;
                int in1 = (q1 < P);
                if (in1) {
                    x1 = __ldg(&pt[3 * q1 + 0]);
                    y1 = __ldg(&pt[3 * q1 + 1]);
                    z1 = __ldg(&pt[3 * q1 + 2]);
                }
                float g0x = Rg[0] * x0 + Rg[1] * y0 + Rg[2] * z0;
                float g0y = Rg[3] * x0 + Rg[4] * y0 + Rg[5] * z0;
                float g0z = Rg[6] * x0 + Rg[7] * y0 + Rg[8] * z0;
                float h0  = 0.5f * (g0x * g0x + g0y * g0y + g0z * g0z);
                float g1x = 0.f, g1y = 0.f, g1z = 0.f, h1 = 3.0e38f;
                if (in1) {
                    g1x = Rg[0] * x1 + Rg[1] * y1 + Rg[2] * z1;
                    g1y = Rg[3] * x1 + Rg[4] * y1 + Rg[5] * z1;
                    g1z = Rg[6] * x1 + Rg[7] * y1 + Rg[8] * z1;
                    h1  = 0.5f * (g1x * g1x + g1y * g1y + g1z * g1z);
                }
                g_gt[b * MAX_P + 2 * i]     = make_float4(g0x, g1x, g0y, g1y);
                g_gt[b * MAX_P + 2 * i + 1] = make_float4(g0z, g1z, h0, h1);
                float p0x = Rp[0] * x0 + Rp[1] * y0 + Rp[2] * z0;
                float p0y = Rp[3] * x0 + Rp[4] * y0 + Rp[5] * z0;
                float p0z = Rp[6] * x0 + Rp[7] * y0 + Rp[8] * z0;
                g_pr[b * MAX_P + q0] = make_float4(p0x, p0y, p0z, 0.f);
                if (in1) {
                    float p1x = Rp[0] * x1 + Rp[1] * y1 + Rp[2] * z1;
                    float p1y = Rp[3] * x1 + Rp[4] * y1 + Rp[5] * z1;
                    float p1z = Rp[6] * x1 + Rp[7] * y1 + Rp[8] * z1;
                    g_pr[b * MAX_P + q1] = make_float4(p1x, p1y, p1z, 0.f);
                }
            }
        }
        __syncthreads();
        __threadfence();
        if (tid == 0) g_ready[b] = valid ? (use_closest ? 3 : 2) : 1;
    }

    // ---------- phase 2: persistent work queue ----------
    int fill_b = -1;

    for (;;) {
        if (tid == 0) s_u[0] = atomicAdd(&g_ctr, 1u);
        __syncthreads();                     // claim barrier; protects sg2/sbest reuse
        unsigned it = s_u[0];
        if (it >= (unsigned)NITEMS) break;

        const int b     = (int)(it / (unsigned)CHUNKS);
        const int chunk = (int)(it % (unsigned)CHUNKS);

        if (tid == 0) {
            volatile int* rdy = g_ready;
            int f = rdy[b];
            while (f == 0) { __nanosleep(64); f = rdy[b]; }
            s_u[1] = (unsigned)f;
        }
        __syncthreads();
        const int flag  = (int)s_u[1];       // 1 skip, 2 direct, 3 closest
        const int pbase = chunk * CHUNK;

        float lsum = 0.f;

        if (flag == 3) {
            // --- this lane's 4 prerotated pred points (4 indep LDG.128) ---
            unsigned long long npxx[4], npyy[4], npzz[4];
#pragma unroll
            for (int j = 0; j < 4; ++j) {
                int p = pbase + lane + 32 * j;
                float4 pp = (p < P) ? g_pr[b * MAX_P + p] : make_float4(0.f, 0.f, 0.f, 0.f);
                npxx[j] = pack2(-pp.x, -pp.x);
                npyy[j] = pack2(-pp.y, -pp.y);
                npzz[j] = pack2(-pp.z, -pp.z);
            }

            const int i0 = (P == 2048) ? wid * 128 : wid * PPW;
            const int i1 = (P == 2048) ? i0 + 128  : min(wid * PPW + PPW, HALF);

            // --- warp-private fill of exactly the slice this warp scans ---
            // (same-warp STS -> LDS is program-ordered; no barrier needed)
            if (fill_b != b) {
                const float4* src = &g_gt[b * MAX_P];
#pragma unroll 8
                for (int e = 2 * i0 + lane; e < 2 * i1; e += 32)
                    sg2[e] = __ldg(&src[e]);
                fill_b = b;
            }

            // --- scan own slice; 4 independent fmin chains ---
            float best[4];
#pragma unroll
            for (int j = 0; j < 4; ++j) best[j] = __uint_as_float(0x7F7FFFFFu);

            const ulonglong2* sgu = reinterpret_cast<const ulonglong2*>(sg2);

            if (P == 2048) {
                const ulonglong2* pg = sgu + 2 * i0;
#pragma unroll 4
                for (int ii = 0; ii < 128; ++ii) {
                    ulonglong2 va = pg[0];
                    ulonglong2 vb = pg[1];
                    pg += 2;
                    SCAN_STEP(va, vb, i0 + ii);
                }
            } else {
#pragma unroll 2
                for (int i = i0; i < i1; ++i) {
                    ulonglong2 va = sgu[2 * i];
                    ulonglong2 vb = sgu[2 * i + 1];
                    SCAN_STEP(va, vb, i);
                }
            }
#pragma unroll
            for (int j = 0; j < 4; ++j)
                sbest[wid * CHUNK + lane + 32 * j] = best[j];
            __syncthreads();                 // also orders all warps' fills for finalize

            // --- thread t (<128) finalizes pred point pbase+t ---
            if (tid < CHUNK) {
                int p = pbase + tid;
                if (p < P) {
                    float m = sbest[tid];
#pragma unroll
                    for (int ww = 1; ww < NW; ++ww)
                        m = fminf(m, sbest[ww * CHUNK + tid]);
                    int k = (int)(__float_as_uint(m) & 0x3FFu);   // pair index

                    float4 pp = g_pr[b * MAX_P + p];
                    float4 A  = sg2[2 * k];
                    float4 Bv = sg2[2 * k + 1];
                    // recompute both t's bit-identically to the FFMA2 path
                    float t0 = fmaf(-pp.x, A.x, fmaf(-pp.y, A.z, fmaf(-pp.z, Bv.x, Bv.z)));
                    float t1 = fmaf(-pp.x, A.y, fmaf(-pp.y, A.w, fmaf(-pp.z, Bv.y, Bv.w)));
                    float gx, gy, gz;
                    if (t1 < t0) { gx = A.y; gy = A.w; gz = Bv.y; }
                    else         { gx = A.x; gy = A.z; gz = Bv.x; }
                    lsum = sl1(pp.x - gx) + sl1(pp.y - gy) + sl1(pp.z - gz);
                }
            }
        } else if (flag == 2) {
            // direct match: p_pred vs p_gt at same index; read scratch, no SMEM
            if (tid < CHUNK) {
                int p = pbase + tid;
                if (p < P) {
                    float4 pp = g_pr[b * MAX_P + p];
                    int k = p >> 1, h = p & 1;
                    float4 A  = g_gt[b * MAX_P + 2 * k];
                    float4 Bv = g_gt[b * MAX_P + 2 * k + 1];
                    float gx = h ? A.y  : A.x;
                    float gy = h ? A.w  : A.z;
                    float gz = h ? Bv.y : Bv.x;
                    lsum = sl1(pp.x - gx) + sl1(pp.y - gy) + sl1(pp.z - gz);
                }
            }
        }

        // deterministic per-item reduce (shuffle tree + fixed-order warp merge)
#pragma unroll
        for (int off = 16; off > 0; off >>= 1)
            lsum += __shfl_down_sync(0xFFFFFFFFu, lsum, off);
        if (lane == 0) sred[wid] = lsum;
        __syncthreads();
        if (tid == 0) {
            float s = 0.f;
#pragma unroll
            for (int ww = 0; ww < NW; ++ww) s += sred[ww];
            g_part[it] = s;
        }
    }

    // ---------- last-block final reduction (fixed order -> deterministic) ----------
    __syncthreads();
    if (tid == 0) {
        __threadfence();
        unsigned d = atomicAdd(&g_done, 1u);
        s_u[0] = (d == gridDim.x - 1) ? 1u : 0u;
    }
    __syncthreads();
    if (s_u[0]) {
        __threadfence();
        float v = 0.f;
        for (int i = tid; i < NITEMS; i += BLK) v += g_part[i];
        sbest[tid] = v;
        __syncthreads();
#pragma unroll
        for (int st = BLK / 2; st > 0; st >>= 1) {
            if (tid < st) sbest[tid] += sbest[tid + st];
            __syncthreads();
        }
        if (tid == 0) {
            out[0] = sbest[0] * inv;
            g_ctr  = 0;
            g_done = 0;
            for (int bb = 0; bb < MAX_B; ++bb) g_ready[bb] = 0;
        }
    }
}

extern "C" void kernel_launch(void* const* d_in, const int* in_sizes, int n_in,
                              void* d_out, int out_size) {
    const float* pred = (const float*)d_in[0];
    const float* tgt  = (const float*)d_in[1];
    const float* w    = (const float*)d_in[2];
    const float* pts  = (const float*)d_in[3];
    const float* sym  = (const float*)d_in[4];

    int C = in_sizes[4];
    int B = in_sizes[0] / (4 * C);
    int P = in_sizes[3] / (3 * C);
    int CHUNKS = (P + CHUNK - 1) / CHUNK;
    int NITEMS = B * CHUNKS;

    pm_all<<<NBLOCKS, BLK>>>(pred, tgt, w, sym, pts,
                             B, C, P, CHUNKS, NITEMS,
                             1.f / (float)(B * P), (float*)d_out);
}

// round 9
// speedup vs baseline: 1.1858x; 1.0626x over previous
#include <cuda_runtime.h>
#include <math.h>

#define BLK      256
#define NW       8          // warps per block
#define CHUNK    128        // pred points per item
#define MAX_P    2048
#define MAX_B    64
#define NBLOCKS  456
#define MAX_ITEMS 4096

// cos(7.5 degrees): ang > 15deg  <=>  |dot| < cos(7.5deg)
#define COS_HALF_HARD 0.9914448613738104f

__device__ unsigned g_ctr  = 0;
__device__ unsigned g_done = 0;
__device__ float    g_part[MAX_ITEMS];

__device__ __forceinline__ float sl1(float v) {
    float a = fabsf(v);
    return (a < 1.f) ? 0.5f * v * v : a - 0.5f;
}

__device__ __forceinline__ void quat2rot(float w, float x, float y, float z, float* R) {
    R[0] = 1.f - 2.f * (y * y + z * z);
    R[1] = 2.f * (x * y - z * w);
    R[2] = 2.f * (x * z + y * w);
    R[3] = 2.f * (x * y + z * w);
    R[4] = 1.f - 2.f * (x * x + z * z);
    R[5] = 2.f * (y * z - x * w);
    R[6] = 2.f * (x * z - y * w);
    R[7] = 2.f * (y * z + x * w);
    R[8] = 1.f - 2.f * (x * x + y * y);
}

// Blackwell packed f32x2 FMA (SASS FFMA2) — only reachable via PTX.
__device__ __forceinline__ unsigned long long ffma2(unsigned long long a,
                                                    unsigned long long b,
                                                    unsigned long long c) {
    unsigned long long d;
    asm("fma.rn.f32x2 %0, %1, %2, %3;" : "=l"(d) : "l"(a), "l"(b), "l"(c));
    return d;
}

__device__ __forceinline__ unsigned long long pack2(float lo, float hi) {
    unsigned long long d;
    asm("mov.b64 %0, {%1, %2};" : "=l"(d)
        : "r"(__float_as_uint(lo)), "r"(__float_as_uint(hi)));
    return d;
}

__device__ __forceinline__ void unpack2(unsigned long long v,
                                        unsigned& lo, unsigned& hi) {
    asm("mov.b64 {%0, %1}, %2;" : "=r"(lo), "=r"(hi) : "l"(v));
}

// one scan step over a q-pair for 4 independent pred chains
#define SCAN_STEP(VA, VB, I)                                               \
    do {                                                                   \
        _Pragma("unroll")                                                  \
        for (int j = 0; j < 4; ++j) {                                      \
            unsigned long long t2 = ffma2(npzz[j], (VB).x, (VB).y);        \
            t2 = ffma2(npyy[j], (VA).y, t2);                               \
            t2 = ffma2(npxx[j], (VA).x, t2);                               \
            unsigned tlo, thi;                                             \
            unpack2(t2, tlo, thi);                                         \
            float m2 = fminf(__uint_as_float(tlo), __uint_as_float(thi));  \
            unsigned km = (__float_as_uint(m2) & 0xFFFFFC00u) | (unsigned)(I); \
            best[j] = fminf(best[j], __uint_as_float(km));                 \
        }                                                                  \
    } while (0)

__global__ void __launch_bounds__(BLK, 3)
pm_fused(const float* __restrict__ pred,
         const float* __restrict__ tgt,
         const float* __restrict__ w,
         const float* __restrict__ sym,
         const float* __restrict__ points,
         int B, int C, int P, int CHUNKS, int NITEMS,
         float inv, float* __restrict__ out) {
    // pair-transposed gt cloud: sg2[2i]   = {gx_q0, gx_q1, gy_q0, gy_q1}
    //                           sg2[2i+1] = {gz_q0, gz_q1, hw_q0, hw_q1}   (q0=2i)
    __shared__ float4   sg2[MAX_P];
    __shared__ float    sbest[NW * CHUNK];   // per-warp packed argmin partials
    __shared__ float    sred[NW];
    __shared__ unsigned s_item;
    __shared__ int      s_list[MAX_B];       // heavy samples first, then the rest
    __shared__ int      s_cls[MAX_B];
    __shared__ unsigned char s_flag[MAX_B];  // 0=skip, 1=direct, 2=closest

    const int tid  = threadIdx.x;
    const int wid  = tid >> 5;
    const int lane = tid & 31;

    // ---------- prologue: every block classifies all samples (redundant, fast) ----
    if (tid < B) {
        const int b = tid;
        int cls = 0, valid = 0;
        // breakless descending scan: all loads independent (high MLP), last
        // assignment = smallest c with weight > 0 (matches argmax(wsel>0))
#pragma unroll 4
        for (int c = C - 1; c >= 0; --c) {
            float wv = __ldg(&w[(size_t)(b * C + c) * 4]);
            if (wv > 0.f) { cls = c; valid = 1; }
        }
        const float* qp = pred + (size_t)(b * C + cls) * 4;
        const float* qg = tgt  + (size_t)(b * C + cls) * 4;
        float pw = __ldg(qp + 0), px_ = __ldg(qp + 1), py_ = __ldg(qp + 2), pz_ = __ldg(qp + 3);
        float gw = __ldg(qg + 0), gx_ = __ldg(qg + 1), gy_ = __ldg(qg + 2), gz_ = __ldg(qg + 3);
        float dot = fabsf(pw * gw + px_ * gx_ + py_ * gy_ + pz_ * gz_);
        int use_closest = (__ldg(&sym[cls]) > 0.f) && (dot < COS_HALF_HARD);
        s_cls[b]  = cls;
        s_flag[b] = (unsigned char)(valid ? (use_closest ? 2 : 1) : 0);
    }
    __syncthreads();
    if (tid == 0) {
        int nh = 0;
        for (int b = 0; b < B; ++b) if (s_flag[b] == 2) s_list[nh++] = b;
        for (int b = 0; b < B; ++b) if (s_flag[b] != 2) s_list[nh++] = b;
    }
    __syncthreads();

    // ---------- persistent queue: heavy items first (list order) ----------
    int   prev_b = -1;   // sample whose Rp/Rg is in registers
    int   fill_b = -1;   // sample whose gt cloud is in SMEM
    float Rp[9], Rg[9];

    const int HALF = (P + 1) >> 1;           // q-pairs
    const int PPW  = (HALF + NW - 1) / NW;   // q-pairs per warp

    for (;;) {
        if (tid == 0) s_item = atomicAdd(&g_ctr, 1u);
        __syncthreads();                     // claim barrier; protects sg2/sbest reuse
        unsigned it = s_item;
        if (it >= (unsigned)NITEMS) break;

        const int b     = s_list[it / (unsigned)CHUNKS];
        const int chunk = (int)(it % (unsigned)CHUNKS);
        const int flag  = s_flag[b];
        const int cls   = s_cls[b];

        if (b != prev_b && flag != 0) {      // uniform across block; no weight scan
            prev_b = b;
            const float* qp = pred + (size_t)(b * C + cls) * 4;
            const float* qg = tgt  + (size_t)(b * C + cls) * 4;
            quat2rot(__ldg(qp + 0), __ldg(qp + 1), __ldg(qp + 2), __ldg(qp + 3), Rp);
            quat2rot(__ldg(qg + 0), __ldg(qg + 1), __ldg(qg + 2), __ldg(qg + 3), Rg);
        }

        float lsum = 0.f;
        const float* pt    = points + (size_t)cls * P * 3;
        const int    pbase = chunk * CHUNK;

        if (flag == 2) {
            // --- rotate + broadcast-pack this lane's 4 pred points ---
            unsigned long long npxx[4], npyy[4], npzz[4];
#pragma unroll
            for (int j = 0; j < 4; ++j) {
                int p = pbase + lane + 32 * j;
                float ppx = 0.f, ppy = 0.f, ppz = 0.f;
                if (p < P) {
                    float x = __ldg(&pt[3 * p + 0]);
                    float y = __ldg(&pt[3 * p + 1]);
                    float z = __ldg(&pt[3 * p + 2]);
                    ppx = Rp[0] * x + Rp[1] * y + Rp[2] * z;
                    ppy = Rp[3] * x + Rp[4] * y + Rp[5] * z;
                    ppz = Rp[6] * x + Rp[7] * y + Rp[8] * z;
                }
                npxx[j] = pack2(-ppx, -ppx);
                npyy[j] = pack2(-ppy, -ppy);
                npzz[j] = pack2(-ppz, -ppz);
            }

            // --- fill pair-transposed gt cloud ---
            if (fill_b != b) {
                for (int i = tid; i < HALF; i += BLK) {
                    int q0 = 2 * i, q1 = 2 * i + 1;
                    float x0 = __ldg(&pt[3 * q0 + 0]);
                    float y0 = __ldg(&pt[3 * q0 + 1]);
                    float z0 = __ldg(&pt[3 * q0 + 2]);
                    float g0x = Rg[0] * x0 + Rg[1] * y0 + Rg[2] * z0;
                    float g0y = Rg[3] * x0 + Rg[4] * y0 + Rg[5] * z0;
                    float g0z = Rg[6] * x0 + Rg[7] * y0 + Rg[8] * z0;
                    float h0  = 0.5f * (g0x * g0x + g0y * g0y + g0z * g0z);
                    float g1x = 0.f, g1y = 0.f, g1z = 0.f, h1 = 3.0e38f;
                    if (q1 < P) {
                        float x1 = __ldg(&pt[3 * q1 + 0]);
                        float y1 = __ldg(&pt[3 * q1 + 1]);
                        float z1 = __ldg(&pt[3 * q1 + 2]);
                        g1x = Rg[0] * x1 + Rg[1] * y1 + Rg[2] * z1;
                        g1y = Rg[3] * x1 + Rg[4] * y1 + Rg[5] * z1;
                        g1z = Rg[6] * x1 + Rg[7] * y1 + Rg[8] * z1;
                        h1  = 0.5f * (g1x * g1x + g1y * g1y + g1z * g1z);
                    }
                    sg2[2 * i]     = make_float4(g0x, g1x, g0y, g1y);
                    sg2[2 * i + 1] = make_float4(g0z, g1z, h0, h1);
                }
                fill_b = b;
            }
            __syncthreads();

            // --- warp scans its q-pair slice; 4 independent fmin chains ---
            float best[4];
#pragma unroll
            for (int j = 0; j < 4; ++j) best[j] = __uint_as_float(0x7F7FFFFFu);

            const ulonglong2* sgu = reinterpret_cast<const ulonglong2*>(sg2);

            if (P == 2048) {
                const int i0 = wid * 128;
                const ulonglong2* pg = sgu + 2 * i0;
#pragma unroll 4
                for (int ii = 0; ii < 128; ++ii) {
                    ulonglong2 va = pg[0];
                    ulonglong2 vb = pg[1];
                    pg += 2;
                    SCAN_STEP(va, vb, i0 + ii);
                }
            } else {
                const int i0 = wid * PPW;
                const int i1 = min(i0 + PPW, HALF);
#pragma unroll 2
                for (int i = i0; i < i1; ++i) {
                    ulonglong2 va = sgu[2 * i];
                    ulonglong2 vb = sgu[2 * i + 1];
                    SCAN_STEP(va, vb, i);
                }
            }
#pragma unroll
            for (int j = 0; j < 4; ++j)
                sbest[wid * CHUNK + lane + 32 * j] = best[j];
            __syncthreads();

            // --- thread t (<128) finalizes pred point pbase+t ---
            if (tid < CHUNK) {
                int p = pbase + tid;
                if (p < P) {
                    float m = sbest[tid];
#pragma unroll
                    for (int ww = 1; ww < NW; ++ww)
                        m = fminf(m, sbest[ww * CHUNK + tid]);
                    int k = (int)(__float_as_uint(m) & 0x3FFu);   // pair index

                    float x = __ldg(&pt[3 * p + 0]);
                    float y = __ldg(&pt[3 * p + 1]);
                    float z = __ldg(&pt[3 * p + 2]);
                    float ppx = Rp[0] * x + Rp[1] * y + Rp[2] * z;
                    float ppy = Rp[3] * x + Rp[4] * y + Rp[5] * z;
                    float ppz = Rp[6] * x + Rp[7] * y + Rp[8] * z;

                    float4 A  = sg2[2 * k];
                    float4 Bv = sg2[2 * k + 1];
                    // recompute both t's bit-identically to the FFMA2 path
                    float t0 = fmaf(-ppx, A.x, fmaf(-ppy, A.z, fmaf(-ppz, Bv.x, Bv.z)));
                    float t1 = fmaf(-ppx, A.y, fmaf(-ppy, A.w, fmaf(-ppz, Bv.y, Bv.w)));
                    float gx, gy, gz;
                    if (t1 < t0) { gx = A.y; gy = A.w; gz = Bv.y; }
                    else         { gx = A.x; gy = A.z; gz = Bv.x; }
                    lsum = sl1(ppx - gx) + sl1(ppy - gy) + sl1(ppz - gz);
                }
            }
        } else if (flag == 1) {
            if (tid < CHUNK) {
                int p = pbase + tid;
                if (p < P) {
                    float x = __ldg(&pt[3 * p + 0]);
                    float y = __ldg(&pt[3 * p + 1]);
                    float z = __ldg(&pt[3 * p + 2]);
                    float ppx = Rp[0] * x + Rp[1] * y + Rp[2] * z;
                    float ppy = Rp[3] * x + Rp[4] * y + Rp[5] * z;
                    float ppz = Rp[6] * x + Rp[7] * y + Rp[8] * z;
                    float gx = Rg[0] * x + Rg[1] * y + Rg[2] * z;
                    float gy = Rg[3] * x + Rg[4] * y + Rg[5] * z;
                    float gz = Rg[6] * x + Rg[7] * y + Rg[8] * z;
                    lsum = sl1(ppx - gx) + sl1(ppy - gy) + sl1(ppz - gz);
                }
            }
        }

        // deterministic per-item reduce (shuffle tree + fixed-order warp merge)
#pragma unroll
        for (int off = 16; off > 0; off >>= 1)
            lsum += __shfl_down_sync(0xFFFFFFFFu, lsum, off);
        if (lane == 0) sred[wid] = lsum;
        __syncthreads();
        if (tid == 0) {
            float s = 0.f;
#pragma unroll
            for (int ww = 0; ww < NW; ++ww) s += sred[ww];
            g_part[it] = s;
        }
    }

    // last-block final reduction (fixed order -> deterministic)
    __syncthreads();
    if (tid == 0) {
        __threadfence();
        unsigned d = atomicAdd(&g_done, 1u);
        s_item = (d == gridDim.x - 1) ? 1u : 0u;
    }
    __syncthreads();
    if (s_item) {
        __threadfence();
        float v = 0.f;
        for (int i = tid; i < NITEMS; i += BLK) v += g_part[i];
        sbest[tid] = v;
        __syncthreads();
#pragma unroll
        for (int st = BLK / 2; st > 0; st >>= 1) {
            if (tid < st) sbest[tid] += sbest[tid + st];
            __syncthreads();
        }
        if (tid == 0) {
            out[0] = sbest[0] * inv;
            g_ctr  = 0;
            g_done = 0;
        }
    }
}

extern "C" void kernel_launch(void* const* d_in, const int* in_sizes, int n_in,
                              void* d_out, int out_size) {
    const float* pred = (const float*)d_in[0];
    const float* tgt  = (const float*)d_in[1];
    const float* w    = (const float*)d_in[2];
    const float* pts  = (const float*)d_in[3];
    const float* sym  = (const float*)d_in[4];

    int C = in_sizes[4];
    int B = in_sizes[0] / (4 * C);
    int P = in_sizes[3] / (3 * C);
    int CHUNKS = (P + CHUNK - 1) / CHUNK;
    int NITEMS = B * CHUNKS;

    pm_fused<<<NBLOCKS, BLK>>>(pred, tgt, w, sym, pts,
                               B, C, P, CHUNKS, NITEMS,
                               1.f / (float)(B * P), (float*)d_out);
}